// round 1
// baseline (speedup 1.0000x reference)
#include <cuda_runtime.h>
#include <cuda_bf16.h>

// Inputs (metadata order):
// 0: nbr_ids   [N]  int32
// 1: seg_ids   [N]  int32   (uniform: i/DEG -- unused, degree derived as N/G)
// 2: batch_idx [G]  int32
// 3: pos_idx   [G]  int32
// 4: s_tem     [B]  int32
// 5: r_tem     [B]  int32
// 6: dt_flat   [G]  float32
// 7: ent_embeds [NUM_ENTS*D] float32
// 8: rel_embeds [NUM_RELS*D] float32
// Output: [ s_embed_seq (B*S*3D floats) | s_hist_dt_seq (B*S floats) ]

// ---------------- Fast path: DEG==32, D==256 ----------------
// 256 threads = 4 groups x 64 lanes; each lane owns one float4 (4 dims).
__global__ void __launch_bounds__(256)
agg_fast_kernel(const int* __restrict__ nbr_ids,
                const int* __restrict__ batch_idx,
                const int* __restrict__ pos_idx,
                const int* __restrict__ s_tem,
                const int* __restrict__ r_tem,
                const float* __restrict__ dt_flat,
                const float4* __restrict__ ent,   // row stride 64 float4
                const float4* __restrict__ rel,   // row stride 64 float4
                float4* __restrict__ out_embed,   // row stride 192 float4
                float* __restrict__ out_dt,
                int S)
{
    const int grp_in_blk = threadIdx.x >> 6;   // 0..3
    const int t          = threadIdx.x & 63;   // float4 lane within row
    const int g          = (blockIdx.x << 2) + grp_in_blk;

    __shared__ int ids[4][32];
    if (t < 32) ids[grp_in_blk][t] = nbr_ids[(g << 5) + t];
    __syncthreads();

    float4 acc = make_float4(0.f, 0.f, 0.f, 0.f);
#pragma unroll
    for (int j = 0; j < 32; ++j) {
        // row offset in float4 units: id * (256/4)
        float4 v = __ldg(&ent[(ids[grp_in_blk][j] << 6) + t]);
        acc.x += v.x; acc.y += v.y; acc.z += v.z; acc.w += v.w;
    }
    const float inv = 1.0f / 32.0f;
    acc.x *= inv; acc.y *= inv; acc.z *= inv; acc.w *= inv;

    const int b = batch_idx[g];
    const int p = pos_idx[g];
    const int obase = (b * S + p) * 192;       // 3*256/4 float4 per row

    float4 sv = __ldg(&ent[(s_tem[b] << 6) + t]);
    float4 rv = __ldg(&rel[(r_tem[b] << 6) + t]);

    out_embed[obase + t]        = acc;
    out_embed[obase + 64 + t]   = sv;
    out_embed[obase + 128 + t]  = rv;

    if (t == 0) out_dt[b * S + p] = dt_flat[g];
}

// ---------------- Generic fallback: any DEG / D ----------------
__global__ void agg_generic_kernel(const int* __restrict__ nbr_ids,
                                   const int* __restrict__ batch_idx,
                                   const int* __restrict__ pos_idx,
                                   const int* __restrict__ s_tem,
                                   const int* __restrict__ r_tem,
                                   const float* __restrict__ dt_flat,
                                   const float* __restrict__ ent,
                                   const float* __restrict__ rel,
                                   float* __restrict__ out_embed,
                                   float* __restrict__ out_dt,
                                   int S, int D, int DEG)
{
    const int g = blockIdx.x;
    const int b = batch_idx[g];
    const int p = pos_idx[g];
    const long obase = (long)(b * S + p) * (3L * D);
    const float inv = 1.0f / (float)DEG;

    for (int d = threadIdx.x; d < D; d += blockDim.x) {
        float sum = 0.f;
        for (int j = 0; j < DEG; ++j) {
            int id = nbr_ids[(long)g * DEG + j];
            sum += ent[(long)id * D + d];
        }
        out_embed[obase + d]         = sum * inv;
        out_embed[obase + D + d]     = ent[(long)s_tem[b] * D + d];
        out_embed[obase + 2 * D + d] = rel[(long)r_tem[b] * D + d];
    }
    if (threadIdx.x == 0) out_dt[b * S + p] = dt_flat[g];
}

extern "C" void kernel_launch(void* const* d_in, const int* in_sizes, int n_in,
                              void* d_out, int out_size)
{
    const int*   nbr_ids   = (const int*)  d_in[0];
    const int*   batch_idx = (const int*)  d_in[2];
    const int*   pos_idx   = (const int*)  d_in[3];
    const int*   s_tem     = (const int*)  d_in[4];
    const int*   r_tem     = (const int*)  d_in[5];
    const float* dt_flat   = (const float*)d_in[6];
    const float* ent       = (const float*)d_in[7];
    const float* rel       = (const float*)d_in[8];

    const int N = in_sizes[0];
    const int G = in_sizes[2];
    const int B = in_sizes[4];
    const int DEG = N / G;
    const int S = G / B;
    // out_size = G*3D + G  =>  D = (out_size/G - 1) / 3
    const int D = ((out_size / G) - 1) / 3;

    float* out_embed = (float*)d_out;
    float* out_dt    = (float*)d_out + (long)G * 3L * D;

    if (DEG == 32 && D == 256 && (G & 3) == 0) {
        agg_fast_kernel<<<G / 4, 256>>>(nbr_ids, batch_idx, pos_idx, s_tem, r_tem,
                                        dt_flat, (const float4*)ent, (const float4*)rel,
                                        (float4*)out_embed, out_dt, S);
    } else {
        agg_generic_kernel<<<G, 256>>>(nbr_ids, batch_idx, pos_idx, s_tem, r_tem,
                                       dt_flat, ent, rel, out_embed, out_dt,
                                       S, D, DEG);
    }
}